// round 8
// baseline (speedup 1.0000x reference)
#include <cuda_runtime.h>
#include <cstdint>

#define BB 64
#define SS 2048
#define II 64
#define HH 128
#define CH 8
#define NCH (SS/CH)
#define MROWS (BB*SS)

typedef unsigned long long ull;

// Scratch + inter-CTA progress flags (no runtime allocation allowed).
__device__ __align__(256) float g_seq0[(size_t)MROWS * HH];
__device__ unsigned g_flag[BB];

// ---------------- packed f32x2 helpers (sm_100+) ----------------
__device__ __forceinline__ ull packf2(float lo, float hi) {
    ull r; asm("mov.b64 %0, {%1, %2};" : "=l"(r) : "f"(lo), "f"(hi)); return r;
}
__device__ __forceinline__ float2 unpackf2(ull v) {
    float2 r; asm("mov.b64 {%0, %1}, %2;" : "=f"(r.x), "=f"(r.y) : "l"(v)); return r;
}
__device__ __forceinline__ ull ffma2(ull a, ull b, ull c) {
    ull d; asm("fma.rn.f32x2 %0, %1, %2, %3;" : "=l"(d) : "l"(a), "l"(b), "l"(c)); return d;
}
__device__ __forceinline__ ull addf2(ull a, ull b) {
    ull d; asm("add.rn.f32x2 %0, %1, %2;" : "=l"(d) : "l"(a), "l"(b)); return d;
}
__device__ __forceinline__ void lds_v2u64(ull &p0, ull &p1, uint32_t addr) {
    asm volatile("ld.shared.v2.u64 {%0, %1}, [%2];" : "=l"(p0), "=l"(p1) : "r"(addr));
}
__device__ __forceinline__ float ex2f(float x) {
    float r; asm("ex2.approx.ftz.f32 %0, %1;" : "=f"(r) : "f"(x)); return r;
}
__device__ __forceinline__ float rcpf(float x) {
    float r; asm("rcp.approx.ftz.f32 %0, %1;" : "=f"(r) : "f"(x)); return r;
}
__device__ __forceinline__ float sigmoidf_(float x) {
    return rcpf(1.0f + ex2f(-1.4426950408889634f * x));
}
__device__ __forceinline__ float tanhf_(float x) {
    float e = ex2f(2.8853900817779268f * x);   // exp(2x)
    return 1.0f - 2.0f * rcpf(e + 1.0f);
}
__device__ __forceinline__ unsigned ld_acquire(const unsigned* p) {
    unsigned v;
    asm volatile("ld.acquire.gpu.global.u32 %0, [%1];" : "=r"(v) : "l"(p) : "memory");
    return v;
}
__device__ __forceinline__ void st_release(unsigned* p, unsigned v) {
    asm volatile("st.release.gpu.global.u32 [%0], %1;" :: "l"(p), "r"(v) : "memory");
}

__global__ void zero_flags() {
    if (threadIdx.x < BB) g_flag[threadIdx.x] = 0;
}

// Quarter-dot: NI iterations of 2x LDS.128 + 4 ffma2 chains, f32x2 add tree.
// Reads 8*NI floats starting at smem byte address `base` against wr[4*NI].
template<int NI>
__device__ __forceinline__ float dot_part(uint32_t base, const ull* wr) {
    ull z = packf2(0.f, 0.f);
    ull a0 = z, a1 = z, a2 = z, a3 = z;
#pragma unroll
    for (int i = 0; i < NI; i++) {
        ull p0, p1, p2, p3;
        lds_v2u64(p0, p1, base + (uint32_t)(i * 32));
        lds_v2u64(p2, p3, base + (uint32_t)(i * 32 + 16));
        a0 = ffma2(p0, wr[4 * i],     a0);
        a1 = ffma2(p1, wr[4 * i + 1], a1);
        a2 = ffma2(p2, wr[4 * i + 2], a2);
        a3 = ffma2(p3, wr[4 * i + 3], a3);
    }
    ull s = addf2(addf2(a0, a1), addf2(a2, a3));
    float2 f = unpackf2(s);
    return f.x + f.y;
}

// ---------------- merged scan+proj role (512 symmetric threads) ----------------
// Thread (q,c): q = lane>>3 (k-quarter), c = warp*8 + (lane&7) (column).
// Per step: quarter of recurrent dot (8 LDS.128 + 16 ffma2) + one row of NEXT
// chunk's input projection (NI iters), both reduced via 2x shfl.bfly so every
// thread holds the full value for its column -> xw stays in a register ring.
// h double-buffered in padded smem; one __syncthreads per step.
// xt double-buffered: rows of chunk m live in xt[m&1]; staged at chunk m-2's
// step 0 from a gmem prefetch issued 3 chunks ahead (flag-gated for consumer).
// Flags are one-directional (producer -> consumer): no cyclic wait possible.
template<int KF, bool PROD>
__device__ __forceinline__ void role(
    float* hs, float* xt,
    const float* __restrict__ xsrc,   // rows of width KF
    const float* __restrict__ u,      // [H,H]
    const float* __restrict__ w,      // [KF,H]
    const float* bg, const float* bu,
    const float* zeta, const float* nu,
    const float* lambd, const float* gamma,
    float* __restrict__ outp,         // [S,H] slice
    float* __restrict__ hl,           // [H] slice
    unsigned* flagp)
{
    constexpr int KQ   = KF / 4;      // values per k-quarter (32 or 16)
    constexpr int KQP  = KQ + 4;      // padded quarter (floats)
    constexpr int XROW = 4 * KQP;     // staged row stride (floats)
    constexpr int XTS  = CH * XROW;   // xt buffer stride (floats)
    constexpr int NV4  = CH * KF / 4; // float4s per staged chunk (<=256)
    constexpr int NI   = KQ / 8;      // dot iterations (4 or 2)

    const int tid  = threadIdx.x;
    const int lane = tid & 31;
    const int wp   = tid >> 5;
    const int q    = lane >> 3;            // k-quarter
    const int c    = wp * 8 + (lane & 7);  // column 0..127

    // Pinned register slices
    ull ureg[16];
#pragma unroll
    for (int m = 0; m < 16; m++) {
        int k0 = 32 * q + 2 * m;
        ureg[m] = packf2(u[(size_t)k0 * HH + c], u[(size_t)(k0 + 1) * HH + c]);
    }
    ull wreg[KQ / 2];
#pragma unroll
    for (int m = 0; m < KQ / 2; m++) {
        int k0 = KQ * q + 2 * m;
        wreg[m] = packf2(w[(size_t)k0 * HH + c], w[(size_t)(k0 + 1) * HH + c]);
    }

    const float bgj = bg[c], buj = bu[c];
    const float sz = sigmoidf_(zeta[0]);
    const float sn = sigmoidf_(nu[0]);
    float gc = gamma[0];
    gc = fminf(fmaxf(gc, 0.0f), 1.0f);
    const float c1 = (1.0f - gc) * lambd[0];

    const uint32_t hb = (uint32_t)__cvta_generic_to_shared(hs);
    const uint32_t xb = (uint32_t)__cvta_generic_to_shared(xt);
    const uint32_t hq = (uint32_t)(q * 36 * 4);   // h quarter byte offset
    const uint32_t xq = (uint32_t)(q * KQP * 4);  // tile quarter byte offset

    // Staging map: thread -> (chunk row, float4 slot)
    const int rowd = tid / (KF / 4);
    const int e    = (tid % (KF / 4)) * 4;
    const int eq   = e / KQ, ew = e % KQ;

    // ---- prologue: rows chunk0 -> xt[0]; xw chunk0; rows1 -> xt[1]; rows2 -> sreg
    float4 sreg = make_float4(0.f, 0.f, 0.f, 0.f);
    if (tid < NV4) {
        if (!PROD) { while (ld_acquire(flagp) < CH) { } }
        sreg = __ldcg(reinterpret_cast<const float4*>(xsrc + (size_t)rowd * KF + e));
        *reinterpret_cast<float4*>(&xt[rowd * XROW + eq * KQP + ew]) = sreg;
    }
    __syncthreads();

    float xwcur[CH], xwnxt[CH];
#pragma unroll
    for (int d = 0; d < CH; d++) {
        float pp = dot_part<NI>(xb + (uint32_t)(d * XROW * 4) + xq, wreg);
        pp += __shfl_xor_sync(0xffffffffu, pp, 8);
        pp += __shfl_xor_sync(0xffffffffu, pp, 16);
        xwcur[d] = pp;
    }
    if (tid < NV4) {
        if (!PROD) { while (ld_acquire(flagp) < 2 * CH) { } }
        sreg = __ldcg(reinterpret_cast<const float4*>(xsrc + (size_t)(CH + rowd) * KF + e));
        *reinterpret_cast<float4*>(&xt[XTS + rowd * XROW + eq * KQP + ew]) = sreg;
        if (!PROD) { while (ld_acquire(flagp) < 3 * CH) { } }
        sreg = __ldcg(reinterpret_cast<const float4*>(xsrc + (size_t)(2 * CH + rowd) * KF + e));
    }
    if (tid < HH) hs[(tid >> 5) * 36 + (tid & 31)] = 0.0f;
    float hprev = 0.0f;
    __syncthreads();

    // ---- main loop
    for (int n = 0; n < NCH; n++) {
        const uint32_t rdoff = ((n + 1) & 1) ? (uint32_t)(XTS * 4) : 0u;  // rows n+1
        const int wrbase = (n & 1) ? XTS : 0;                             // rows n+2
#pragma unroll
        for (int d = 0; d < CH; d++) {
            if (d == 0) {
                if (tid < NV4) {
                    *reinterpret_cast<float4*>(
                        &xt[wrbase + rowd * XROW + eq * KQP + ew]) = sreg;
                    const int r3 = (n + 3) * CH;
                    if (r3 < SS) {
                        if (!PROD) {
                            unsigned need = (unsigned)(r3 + CH);
                            if (need > SS) need = SS;
                            while (ld_acquire(flagp) < need) { }
                        }
                        sreg = __ldcg(reinterpret_cast<const float4*>(
                            xsrc + (size_t)(r3 + rowd) * KF + e));
                    }
                }
            }
            // input projection for chunk n+1, row d (register result)
            float pp = dot_part<NI>(xb + rdoff + (uint32_t)(d * XROW * 4) + xq, wreg);
            pp += __shfl_xor_sync(0xffffffffu, pp, 8);
            pp += __shfl_xor_sync(0xffffffffu, pp, 16);
            xwnxt[d] = pp;

            // recurrent step t
            const int t = n * CH + d;
            float part = dot_part<4>(hb + ((t & 1) ? 576u : 0u) + hq, ureg);
            part += __shfl_xor_sync(0xffffffffu, part, 8);
            part += __shfl_xor_sync(0xffffffffu, part, 16);
            float pre = part + xwcur[d];

            float z  = sigmoidf_(pre + bgj);
            float hh = tanhf_(pre + buj);
            float hn = z * hprev + (sz * (1.0f - z) + sn) * hh;
            float hc = gc * hn + c1;

            if (lane < 8) {
                hs[((t & 1) ^ 1) * 144 + (c >> 5) * 36 + (c & 31)] = hc;
                outp[(size_t)t * HH + c] = hc;
            }
            hprev = hc;
            __syncthreads();
        }
        if (PROD) {
            __threadfence();
            __syncthreads();
            if (tid == 0) st_release(flagp, (unsigned)((n + 1) * CH));
        }
#pragma unroll
        for (int d = 0; d < CH; d++) xwcur[d] = xwnxt[d];
    }
    if (lane < 8) hl[c] = hprev;
}

// ---------------- fused persistent kernel: 64 producer + 64 consumer CTAs
__global__ void __launch_bounds__(512, 1) fused_grnn(
    const float* __restrict__ x,
    const float* __restrict__ u0, const float* __restrict__ w0,
    const float* __restrict__ bg0, const float* __restrict__ bu0,
    const float* __restrict__ zeta0, const float* __restrict__ nu0,
    const float* __restrict__ lambd0, const float* __restrict__ gamma0,
    const float* __restrict__ u1, const float* __restrict__ w1,
    const float* __restrict__ bg1, const float* __restrict__ bu1,
    const float* __restrict__ zeta1, const float* __restrict__ nu1,
    const float* __restrict__ lambd1, const float* __restrict__ gamma1,
    float* __restrict__ out1, float* __restrict__ hn)
{
    __shared__ __align__(16) float hs[2 * 144];            // 2 x (4 x 36)
    __shared__ __align__(16) float xt[2 * CH * 144];       // max XROW = 144

    const int rank = blockIdx.x;
    if (rank < BB) {
        const int b = rank;
        role<II, true>(hs, xt,
            x + (size_t)b * SS * II, u0, w0,
            bg0, bu0, zeta0, nu0, lambd0, gamma0,
            (float*)g_seq0 + (size_t)b * SS * HH,
            hn + (size_t)b * HH,
            &g_flag[b]);
    } else {
        const int b = rank - BB;
        role<HH, false>(hs, xt,
            (const float*)g_seq0 + (size_t)b * SS * HH, u1, w1,
            bg1, bu1, zeta1, nu1, lambd1, gamma1,
            out1 + (size_t)b * SS * HH,
            hn + (size_t)(BB + b) * HH,
            &g_flag[b]);
    }
}

// ---------------- launch ----------------
extern "C" void kernel_launch(void* const* d_in, const int* in_sizes, int n_in,
                              void* d_out, int out_size)
{
    const float* x      = (const float*)d_in[0];
    const float* w0     = (const float*)d_in[1];
    const float* u0     = (const float*)d_in[2];
    const float* bg0    = (const float*)d_in[3];
    const float* bu0    = (const float*)d_in[4];
    const float* zeta0  = (const float*)d_in[5];
    const float* nu0    = (const float*)d_in[6];
    const float* lambd0 = (const float*)d_in[7];
    const float* gamma0 = (const float*)d_in[8];
    const float* w1     = (const float*)d_in[9];
    const float* u1     = (const float*)d_in[10];
    const float* bg1    = (const float*)d_in[11];
    const float* bu1    = (const float*)d_in[12];
    const float* zeta1  = (const float*)d_in[13];
    const float* nu1    = (const float*)d_in[14];
    const float* lambd1 = (const float*)d_in[15];
    const float* gamma1 = (const float*)d_in[16];

    float* out1 = (float*)d_out;                          // [B,S,H]
    float* hn   = out1 + (size_t)BB * SS * HH;            // [2,B,H]

    zero_flags<<<1, 64>>>();
    fused_grnn<<<2 * BB, 512>>>(x,
        u0, w0, bg0, bu0, zeta0, nu0, lambd0, gamma0,
        u1, w1, bg1, bu1, zeta1, nu1, lambd1, gamma1,
        out1, hn);
}